// round 16
// baseline (speedup 1.0000x reference)
#include <cuda_runtime.h>

// out[i, c] = max_{k<7} x[hex_idx[i,k], c]  for i < L = out_size / 512
// hex_idx is int32 on disk (JAX silently downgrades int64 without x64 mode).
//
// CONVERGED FINAL (6 samples: 14.78/14.82/14.85/14.88/15.36/17.09us timed,
// median ~14.87; ncu-profiled duration invariant 17.6-18.2us across all
// variants -> timed spread is board-state noise). Structural floor: ~168MB
// irreducible L2 traffic per launch (147MB gather + 21MB store) at the
// path-independent LTS cap (~6300 B/cyc ≈ 11.4TB/s effective). x (84MB)
// stays L2-resident across graph replays; .cs output stores don't evict it.
//
//   - one-shot CTAs (5121), 128 threads = 2 output rows per CTA
//   - 64 threads x 32B chunks cover one 2048B row (perfectly coalesced)
//   - 7 independent 256-bit ld.global.nc.v4.b64 gathers per thread (MLP=7)
//   - 2x 128-bit st.global.cs streaming stores
//
// Axes swept and closed (R2-R15): CTA size {64,128,256} -> 128; persistent
// grid-stride -> worse (serializes per-warp MLP); 128-bit gathers -> worse;
// L2::evict_last -> neutral; 256-bit packed store -> worse (tail pack-ALU);
// occupancy LSU-queue-pinned ~52% regardless of theoretical ceiling;
// scatter-max inversion -> >300us atomics; bf16 compression -> rel-err;
// TMA/multicast/clustering -> no deterministic sharing in random indices,
// LTS cap is path-independent; index sort -> costs more traffic than saved.

static constexpr int K = 7;

struct F8 { float f[8]; };

__device__ __forceinline__ F8 ldg_nc_256(const char* base, unsigned off) {
    unsigned long long r0, r1, r2, r3;
    asm("ld.global.nc.v4.b64 {%0,%1,%2,%3}, [%4];"
        : "=l"(r0), "=l"(r1), "=l"(r2), "=l"(r3)
        : "l"(base + off));
    F8 v;
    v.f[0] = __uint_as_float((unsigned)(r0 & 0xffffffffu));
    v.f[1] = __uint_as_float((unsigned)(r0 >> 32));
    v.f[2] = __uint_as_float((unsigned)(r1 & 0xffffffffu));
    v.f[3] = __uint_as_float((unsigned)(r1 >> 32));
    v.f[4] = __uint_as_float((unsigned)(r2 & 0xffffffffu));
    v.f[5] = __uint_as_float((unsigned)(r2 >> 32));
    v.f[6] = __uint_as_float((unsigned)(r3 & 0xffffffffu));
    v.f[7] = __uint_as_float((unsigned)(r3 >> 32));
    return v;
}

__device__ __forceinline__ void stg_cs_128(float* p, float a, float b, float c, float d) {
    asm volatile("st.global.cs.v4.f32 [%0], {%1,%2,%3,%4};"
                 :: "l"(p), "f"(a), "f"(b), "f"(c), "f"(d)
                 : "memory");
}

__global__ void __launch_bounds__(128)
hex_pool_kernel(const char* __restrict__ x,      // (N, 2048 bytes) rows
                const int*  __restrict__ hex_idx,
                float*      __restrict__ out,    // (L, 512) floats
                int L)
{
    // 2 rows per CTA: threads 0..63 -> row 2b, 64..127 -> row 2b+1.
    const int half = threadIdx.x >> 6;      // 0 or 1
    const int c    = threadIdx.x & 63;      // 32B chunk within row
    const int i    = blockIdx.x * 2 + half;
    if (i >= L) return;

    const int* r = hex_idx + i * K;
    int j[K];
#pragma unroll
    for (int k = 0; k < K; k++) j[k] = __ldg(r + k);

    const unsigned coff = (unsigned)c * 32u;

    // 7 independent 256-bit gathers in flight before any consumption.
    F8 v[K];
#pragma unroll
    for (int k = 0; k < K; k++)
        v[k] = ldg_nc_256(x, (unsigned)j[k] * 2048u + coff);

    float m[8];
#pragma unroll
    for (int e = 0; e < 8; e++) {
        float t = v[0].f[e];
#pragma unroll
        for (int k = 1; k < K; k++) t = fmaxf(t, v[k].f[e]);
        m[e] = t;
    }

    float* op = out + (unsigned)i * 512u + (unsigned)c * 8u;
    stg_cs_128(op,     m[0], m[1], m[2], m[3]);
    stg_cs_128(op + 4, m[4], m[5], m[6], m[7]);
}

extern "C" void kernel_launch(void* const* d_in, const int* in_sizes, int n_in,
                              void* d_out, int out_size)
{
    const char* x   = (const char*)d_in[0];  // (N, 512) float32 rows
    const int*  idx = (const int*)d_in[1];   // (N, 7) int32
    float*      out = (float*)d_out;         // (L, 512) float32

    int L = out_size / 512;                  // 10242
    int grid = (L + 1) / 2;                  // 5121 one-shot CTAs

    hex_pool_kernel<<<grid, 128>>>(x, idx, out, L);
}

// round 17
// speedup vs baseline: 1.0173x; 1.0173x over previous
#include <cuda_runtime.h>

// out[i, c] = max_{k<7} x[hex_idx[i,k], c]  for i < L = out_size / 512
// hex_idx is int32 on disk (JAX silently downgrades int64 without x64 mode).
//
// CONVERGED FINAL (7 samples of this config: 14.78/14.82/14.85/14.88/15.07/
// 15.36/17.09us timed; ncu-profiled duration invariant 17.6-18.2us across
// ALL variants -> timed spread is board clock state, not code).
// Structural floor: ~168MB irreducible L2 traffic per launch (147MB gather
// + 21MB store) at the path-independent LTS cap (~6300 B/cyc ≈ 11.4TB/s).
// x (84MB) stays L2-resident across graph replays; .cs stores don't evict it.
//
//   - one-shot CTAs (5121), 128 threads = 2 output rows per CTA
//   - 64 threads x 32B chunks cover one 2048B row (perfectly coalesced)
//   - 7 independent 256-bit ld.global.nc.v4.b64 gathers per thread (MLP=7)
//   - 2x 128-bit st.global.cs streaming stores
//
// Search space closed (R2-R16): CTA size {64,128,256} -> 128 best;
// persistent grid-stride -> worse (serializes per-warp MLP); 128-bit
// gathers -> worse (half bytes per LSU slot); L2::evict_last -> neutral;
// 256-bit packed store -> worse (tail pack-ALU); clamp/guard -> neutral;
// occupancy LSU-queue-pinned ~52% regardless of theoretical ceiling;
// scatter-max inversion -> >300us of atomics; bf16 compression -> breaks
// 1e-3 rel-err; TMA/multicast -> no deterministic sharing in random
// indices and the LTS cap is path-independent; index sort -> extra pass
// costs more than it saves inside an L2-resident working set.

static constexpr int K = 7;

struct F8 { float f[8]; };

__device__ __forceinline__ F8 ldg_nc_256(const char* base, unsigned off) {
    unsigned long long r0, r1, r2, r3;
    asm("ld.global.nc.v4.b64 {%0,%1,%2,%3}, [%4];"
        : "=l"(r0), "=l"(r1), "=l"(r2), "=l"(r3)
        : "l"(base + off));
    F8 v;
    v.f[0] = __uint_as_float((unsigned)(r0 & 0xffffffffu));
    v.f[1] = __uint_as_float((unsigned)(r0 >> 32));
    v.f[2] = __uint_as_float((unsigned)(r1 & 0xffffffffu));
    v.f[3] = __uint_as_float((unsigned)(r1 >> 32));
    v.f[4] = __uint_as_float((unsigned)(r2 & 0xffffffffu));
    v.f[5] = __uint_as_float((unsigned)(r2 >> 32));
    v.f[6] = __uint_as_float((unsigned)(r3 & 0xffffffffu));
    v.f[7] = __uint_as_float((unsigned)(r3 >> 32));
    return v;
}

__device__ __forceinline__ void stg_cs_128(float* p, float a, float b, float c, float d) {
    asm volatile("st.global.cs.v4.f32 [%0], {%1,%2,%3,%4};"
                 :: "l"(p), "f"(a), "f"(b), "f"(c), "f"(d)
                 : "memory");
}

__global__ void __launch_bounds__(128)
hex_pool_kernel(const char* __restrict__ x,      // (N, 2048 bytes) rows
                const int*  __restrict__ hex_idx,
                float*      __restrict__ out,    // (L, 512) floats
                int L)
{
    // 2 rows per CTA: threads 0..63 -> row 2b, 64..127 -> row 2b+1.
    const int half = threadIdx.x >> 6;      // 0 or 1
    const int c    = threadIdx.x & 63;      // 32B chunk within row
    const int i    = blockIdx.x * 2 + half;
    if (i >= L) return;

    const int* r = hex_idx + i * K;
    int j[K];
#pragma unroll
    for (int k = 0; k < K; k++) j[k] = __ldg(r + k);

    const unsigned coff = (unsigned)c * 32u;

    // 7 independent 256-bit gathers in flight before any consumption.
    F8 v[K];
#pragma unroll
    for (int k = 0; k < K; k++)
        v[k] = ldg_nc_256(x, (unsigned)j[k] * 2048u + coff);

    float m[8];
#pragma unroll
    for (int e = 0; e < 8; e++) {
        float t = v[0].f[e];
#pragma unroll
        for (int k = 1; k < K; k++) t = fmaxf(t, v[k].f[e]);
        m[e] = t;
    }

    float* op = out + (unsigned)i * 512u + (unsigned)c * 8u;
    stg_cs_128(op,     m[0], m[1], m[2], m[3]);
    stg_cs_128(op + 4, m[4], m[5], m[6], m[7]);
}

extern "C" void kernel_launch(void* const* d_in, const int* in_sizes, int n_in,
                              void* d_out, int out_size)
{
    const char* x   = (const char*)d_in[0];  // (N, 512) float32 rows
    const int*  idx = (const int*)d_in[1];   // (N, 7) int32
    float*      out = (float*)d_out;         // (L, 512) float32

    int L = out_size / 512;                  // 10242
    int grid = (L + 1) / 2;                  // 5121 one-shot CTAs

    hex_pool_kernel<<<grid, 128>>>(x, idx, out, L);
}